// round 1
// baseline (speedup 1.0000x reference)
#include <cuda_runtime.h>
#include <math.h>

#define Bb   2
#define Tt   512
#define DMm  1024
#define Hh   16
#define DHh  64
#define Dd   32
#define Rr   4
#define BHT  (Bb*Hh*Tt)   /* 16384 */

#define TQ 128
#define TJ 64
#define USTRIDE 132

// ---------------- scratch (device globals; no allocation allowed) ----------
__device__ float g_q [BHT*DHh];
__device__ float g_k [BHT*DHh];
__device__ float g_v [BHT*DHh];
__device__ float g_qm[BHT*Dd];
__device__ float g_km[BHT*Dd];
__device__ float g_q2[BHT];
__device__ float g_k2[BHT];
__device__ float g_U [BHT*Dd*Rr];
__device__ float g_Uq[BHT*Rr];
__device__ float g_ao[Bb*Tt*DMm];

// ---------------- GEMM: C[1024,1024] = A @ W  -------------------------------
// mode 0: A = x, W selected by blockIdx.z (Wq/Wk/Wv), output head-split to g_q/g_k/g_v
// mode 1: A = g_ao, W = W0 (Wo), output plain row-major to Cout
__global__ void __launch_bounds__(256) gemm_kernel(
    const float* __restrict__ A,
    const float* __restrict__ W0, const float* __restrict__ W1,
    const float* __restrict__ W2,
    float* __restrict__ Cout, int mode)
{
    __shared__ float sA[16][64];
    __shared__ float sB[16][64];

    const float* Aptr = (mode == 0) ? A : g_ao;
    const float* Wm   = (mode == 0)
        ? (blockIdx.z == 0 ? W0 : (blockIdx.z == 1 ? W1 : W2))
        : W0;

    int tid = threadIdx.x;
    int tx  = tid & 15;
    int ty  = tid >> 4;
    int row0 = blockIdx.y * 64;
    int col0 = blockIdx.x * 64;

    float acc[4][4];
    #pragma unroll
    for (int i = 0; i < 4; i++)
        #pragma unroll
        for (int j = 0; j < 4; j++) acc[i][j] = 0.f;

    int ar = tid >> 2, ak = (tid & 3) << 2;   // A: 64 rows x 16 k
    int br = tid >> 4, bc = (tid & 15) << 2;  // B: 16 rows x 64 cols

    for (int k0 = 0; k0 < 1024; k0 += 16) {
        float4 av4 = *(const float4*)&Aptr[(row0 + ar) * 1024 + k0 + ak];
        float4 bv4 = *(const float4*)&Wm[(k0 + br) * 1024 + col0 + bc];
        __syncthreads();
        sA[ak + 0][ar] = av4.x;
        sA[ak + 1][ar] = av4.y;
        sA[ak + 2][ar] = av4.z;
        sA[ak + 3][ar] = av4.w;
        *(float4*)&sB[br][bc] = bv4;
        __syncthreads();
        #pragma unroll
        for (int k = 0; k < 16; k++) {
            float4 a = *(const float4*)&sA[k][ty * 4];
            float4 b = *(const float4*)&sB[k][tx * 4];
            float ai[4] = {a.x, a.y, a.z, a.w};
            float bj[4] = {b.x, b.y, b.z, b.w};
            #pragma unroll
            for (int i = 0; i < 4; i++)
                #pragma unroll
                for (int j = 0; j < 4; j++)
                    acc[i][j] += ai[i] * bj[j];
        }
    }

    if (mode == 1) {
        #pragma unroll
        for (int i = 0; i < 4; i++) {
            int r = row0 + ty * 4 + i;
            float4 o = make_float4(acc[i][0], acc[i][1], acc[i][2], acc[i][3]);
            *(float4*)&Cout[r * 1024 + col0 + tx * 4] = o;
        }
    } else {
        float* dst = (blockIdx.z == 0) ? g_q : (blockIdx.z == 1) ? g_k : g_v;
        int h = col0 >> 6;            // col tile 64-aligned => single head
        int dh0 = (col0 & 63) + tx * 4;
        #pragma unroll
        for (int i = 0; i < 4; i++) {
            int r = row0 + ty * 4 + i;
            int b = r >> 9, t = r & 511;
            float4 o = make_float4(acc[i][0], acc[i][1], acc[i][2], acc[i][3]);
            *(float4*)&dst[(((b << 4) + h) * 512 + t) * 64 + dh0] = o;
        }
    }
}

// ---------------- RoPE (in place on g_q, g_k) -------------------------------
__global__ void rope_kernel()
{
    int idx = blockIdx.x * blockDim.x + threadIdx.x;
    if (idx >= BHT * 32) return;
    int tok = idx >> 5;
    int j   = idx & 31;
    int t   = tok & 511;
    // inv_freq = 10000^(-2j/64)
    float inv = expf(-((float)(2 * j) / 64.0f) * 9.210340371976184f);
    float fr  = (float)t * inv;
    float s, c;
    sincosf(fr, &s, &c);

    float* q = g_q + tok * 64;
    float x1 = q[j], x2 = q[j + 32];
    q[j]      = x1 * c - x2 * s;
    q[j + 32] = x1 * s + x2 * c;

    float* k = g_k + tok * 64;
    x1 = k[j]; x2 = k[j + 32];
    k[j]      = x1 * c - x2 * s;
    k[j + 32] = x1 * s + x2 * c;
}

// ---------------- metric: qm, km, q2, k2, U, Uq -----------------------------
__global__ void __launch_bounds__(256) metric_kernel(
    const float* __restrict__ Wqm, const float* __restrict__ Wkm,
    const float* __restrict__ Wmetric)
{
    __shared__ float sWqm[64 * 32];
    __shared__ float sWkm[64 * 32];
    __shared__ float sWm [32 * 128];
    int tid = threadIdx.x;
    for (int i = tid; i < 64 * 32; i += 256) { sWqm[i] = Wqm[i]; sWkm[i] = Wkm[i]; }
    for (int i = tid; i < 32 * 128; i += 256) { sWm[i] = Wmetric[i]; }
    __syncthreads();

    const unsigned FULL = 0xffffffffu;
    int w = tid >> 5, lane = tid & 31;
    int tok = blockIdx.x * 8 + w;

    const float* q = g_q + tok * 64;
    const float* k = g_k + tok * 64;
    float a0 = q[lane], a1 = q[lane + 32];
    float b0 = k[lane], b1 = k[lane + 32];

    float accq = 0.f, acck = 0.f;
    #pragma unroll
    for (int d = 0; d < 32; d++) {
        float qd = __shfl_sync(FULL, a0, d);
        float kd = __shfl_sync(FULL, b0, d);
        accq += qd * sWqm[d * 32 + lane];
        acck += kd * sWkm[d * 32 + lane];
    }
    #pragma unroll
    for (int d = 0; d < 32; d++) {
        float qd = __shfl_sync(FULL, a1, d);
        float kd = __shfl_sync(FULL, b1, d);
        accq += qd * sWqm[(d + 32) * 32 + lane];
        acck += kd * sWkm[(d + 32) * 32 + lane];
    }
    float qmv = 1.f / (1.f + expf(-accq));
    float kmv = 1.f / (1.f + expf(-acck));
    g_qm[tok * 32 + lane] = qmv;
    g_km[tok * 32 + lane] = kmv;

    float q2 = qmv * qmv, k2 = kmv * kmv;
    #pragma unroll
    for (int o = 16; o > 0; o >>= 1) {
        q2 += __shfl_xor_sync(FULL, q2, o);
        k2 += __shfl_xor_sync(FULL, k2, o);
    }
    if (lane == 0) { g_q2[tok] = q2; g_k2[tok] = k2; }

    // U[tok, d=lane, r=0..3] = sum_dd qm[dd] * Wmetric[dd, lane*4+r]
    float u0 = 0.f, u1 = 0.f, u2 = 0.f, u3 = 0.f;
    #pragma unroll
    for (int d = 0; d < 32; d++) {
        float qd = __shfl_sync(FULL, qmv, d);
        float4 wv = *(const float4*)&sWm[d * 128 + lane * 4];
        u0 += qd * wv.x; u1 += qd * wv.y; u2 += qd * wv.z; u3 += qd * wv.w;
    }
    *(float4*)&g_U[tok * 128 + lane * 4] = make_float4(u0, u1, u2, u3);

    float p0 = u0 * qmv, p1 = u1 * qmv, p2 = u2 * qmv, p3 = u3 * qmv;
    #pragma unroll
    for (int o = 16; o > 0; o >>= 1) {
        p0 += __shfl_xor_sync(FULL, p0, o);
        p1 += __shfl_xor_sync(FULL, p1, o);
        p2 += __shfl_xor_sync(FULL, p2, o);
        p3 += __shfl_xor_sync(FULL, p3, o);
    }
    if (lane == 0) {
        g_Uq[tok * 4 + 0] = p0; g_Uq[tok * 4 + 1] = p1;
        g_Uq[tok * 4 + 2] = p2; g_Uq[tok * 4 + 3] = p3;
    }
}

// ---------------- attention -------------------------------------------------
// block: (qtile, bh). 256 threads = 128 queries x 2 halves (even/odd j-tiles).
__global__ void __launch_bounds__(256, 1) attn_kernel(const float* __restrict__ temp_ptr)
{
    extern __shared__ float sm[];
    float* sU  = sm;                        // TQ*USTRIDE
    float* sKm = sU + TQ * USTRIDE;         // 2 * TJ*32
    float* sV  = sKm + 2 * TJ * 32;         // 2 * TJ*64
    float* sK2 = sV + 2 * TJ * 64;          // 2 * TJ

    int bh = blockIdx.y;
    int b = bh >> 4, h = bh & 15;
    int qt = blockIdx.x;
    int tid = threadIdx.x;
    int qi = tid & 127;
    int half = tid >> 7;
    int i = qt * TQ + qi;
    int tokBase = bh * Tt;
    int tok = tokBase + i;

    float qm[32];
    #pragma unroll
    for (int d = 0; d < 32; d++) qm[d] = g_qm[tok * 32 + d];
    float Uq0 = g_Uq[tok * 4 + 0], Uq1 = g_Uq[tok * 4 + 1];
    float Uq2 = g_Uq[tok * 4 + 2], Uq3 = g_Uq[tok * 4 + 3];
    float q2  = g_q2[tok];
    float invT = 1.0f / fmaxf(temp_ptr[0], 0.5f);

    // stage U tile for this block's queries (stride 132 -> conflict-free f4)
    for (int idx = tid; idx < TQ * 32; idx += 256) {
        int r = idx >> 5, c4 = idx & 31;
        float4 v = *(const float4*)&g_U[(tokBase + qt * TQ + r) * 128 + c4 * 4];
        *(float4*)&sU[r * USTRIDE + c4 * 4] = v;
    }

    float acc[64];
    #pragma unroll
    for (int c = 0; c < 64; c++) acc[c] = 0.f;
    float lsum = 0.f;

    float* myKm = sKm + half * TJ * 32;
    float* myV  = sV  + half * TJ * 64;
    float* myK2 = sK2 + half * TJ;
    int lt = tid & 127;

    int nS = qt + 1;                 // each half processes qt+1 tiles
    for (int s = 0; s < nS; s++) {
        int jt = 2 * s + half;
        int j0 = jt * TJ;
        __syncthreads();
        {
            int tokJ = tokBase + j0;
            #pragma unroll
            for (int p = 0; p < 4; p++) {
                int e = lt + p * 128;                    // 512 f4 of km
                *(float4*)&myKm[e * 4] = *(const float4*)&g_km[tokJ * 32 + e * 4];
            }
            #pragma unroll
            for (int p = 0; p < 8; p++) {
                int e = lt + p * 128;                    // 1024 f4 of v
                *(float4*)&myV[e * 4] = *(const float4*)&g_v[tokJ * 64 + e * 4];
            }
            if (lt < TJ) myK2[lt] = g_k2[tokJ + lt];
        }
        __syncthreads();

        if (j0 <= i) {
            int jend = min(TJ, i - j0 + 1);
            for (int jj = 0; jj < jend; jj++) {
                const float4* km4 = (const float4*)&myKm[jj * 32];
                float qk = 0.f, u0b = 0.f, u1b = 0.f, u2b = 0.f, u3b = 0.f;
                #pragma unroll
                for (int dd = 0; dd < 8; dd++) {
                    float4 kv = km4[dd];
                    qk += qm[dd*4+0]*kv.x + qm[dd*4+1]*kv.y
                        + qm[dd*4+2]*kv.z + qm[dd*4+3]*kv.w;
                    float4 Ua = *(const float4*)&sU[qi*USTRIDE + (dd*4+0)*4];
                    float4 Ub = *(const float4*)&sU[qi*USTRIDE + (dd*4+1)*4];
                    float4 Uc = *(const float4*)&sU[qi*USTRIDE + (dd*4+2)*4];
                    float4 Ud = *(const float4*)&sU[qi*USTRIDE + (dd*4+3)*4];
                    u0b += kv.x*Ua.x + kv.y*Ub.x + kv.z*Uc.x + kv.w*Ud.x;
                    u1b += kv.x*Ua.y + kv.y*Ub.y + kv.z*Uc.y + kv.w*Ud.y;
                    u2b += kv.x*Ua.z + kv.y*Ub.z + kv.z*Uc.z + kv.w*Ud.z;
                    u3b += kv.x*Ua.w + kv.y*Ub.w + kv.z*Uc.w + kv.w*Ud.w;
                }
                float e0 = Uq0-u0b, e1 = Uq1-u1b, e2 = Uq2-u2b, e3 = Uq3-u3b;
                float dist = q2 + myK2[jj] - 2.f*qk + e0*e0 + e1*e1 + e2*e2 + e3*e3;
                dist = fmaxf(dist, 0.f);
                float p = expf(-dist * invT);     // logit <= 0, no max-tracking needed
                lsum += p;
                const float4* v4 = (const float4*)&myV[jj * 64];
                #pragma unroll
                for (int c = 0; c < 16; c++) {
                    float4 vv = v4[c];
                    acc[c*4+0] += p*vv.x; acc[c*4+1] += p*vv.y;
                    acc[c*4+2] += p*vv.z; acc[c*4+3] += p*vv.w;
                }
            }
        }
    }

    __syncthreads();
    if (half == 1) {
        float* mb = sU + qi * 66;     // reuse U region as merge buffer
        #pragma unroll
        for (int c = 0; c < 64; c++) mb[c] = acc[c];
        mb[64] = lsum;
    }
    __syncthreads();
    if (half == 0) {
        const float* mb = sU + qi * 66;
        lsum += mb[64];
        float inv = 1.f / lsum;
        float* outp = g_ao + ((size_t)(b * Tt + i)) * DMm + h * 64;
        #pragma unroll
        for (int c = 0; c < 64; c += 4) {
            float4 o;
            o.x = (acc[c+0] + mb[c+0]) * inv;
            o.y = (acc[c+1] + mb[c+1]) * inv;
            o.z = (acc[c+2] + mb[c+2]) * inv;
            o.w = (acc[c+3] + mb[c+3]) * inv;
            *(float4*)&outp[c] = o;
        }
    }
}

// ---------------- launch -----------------------------------------------------
extern "C" void kernel_launch(void* const* d_in, const int* in_sizes, int n_in,
                              void* d_out, int out_size)
{
    const float* x      = (const float*)d_in[0];
    const float* Wq     = (const float*)d_in[1];
    const float* Wk     = (const float*)d_in[2];
    const float* Wv     = (const float*)d_in[3];
    const float* Wo     = (const float*)d_in[4];
    const float* Wqm    = (const float*)d_in[5];
    const float* Wkm    = (const float*)d_in[6];
    const float* Wmet   = (const float*)d_in[7];
    const float* temp   = (const float*)d_in[8];
    float*       out    = (float*)d_out;

    const int smem_bytes = (TQ*USTRIDE + 2*TJ*32 + 2*TJ*64 + 2*TJ) * 4; // 117248
    cudaFuncSetAttribute(attn_kernel,
                         cudaFuncAttributeMaxDynamicSharedMemorySize, smem_bytes);

    // 1) QKV projections (head-split store)
    gemm_kernel<<<dim3(16, 16, 3), 256>>>(x, Wq, Wk, Wv, nullptr, 0);
    // 2) RoPE
    rope_kernel<<<(BHT * 32) / 256, 256>>>();
    // 3) metric projections
    metric_kernel<<<BHT / 8, 256>>>(Wqm, Wkm, Wmet);
    // 4) attention
    attn_kernel<<<dim3(Tt / TQ, Bb * Hh), 256, smem_bytes>>>(temp);
    // 5) output projection
    gemm_kernel<<<dim3(16, 16, 1), 256>>>(nullptr, Wo, nullptr, nullptr, out, 1);
}